// round 1
// baseline (speedup 1.0000x reference)
#include <cuda_runtime.h>
#include <cuda_bf16.h>

#define B_ 4
#define N_ 2048
#define D_ 1024
#define M_TOT (B_ * N_)

// Static scratch (device-global arrays: allocation-free per harness rules)
__device__ float g_Q[M_TOT * D_];          // 32 MB
__device__ float g_K[M_TOT * D_];          // 32 MB
__device__ float g_V[M_TOT * D_];          // 32 MB
__device__ float g_S[(size_t)B_ * N_ * N_]; // 64 MB

// ---------------------------------------------------------------------------
// Kernel 1: Q/K/V = x @ W   (M=8192, K=1024, N=1024), blockIdx.z picks W.
// 128x128x8 tile, 256 threads, 8x8 microtile per thread.
// ---------------------------------------------------------------------------
__global__ __launch_bounds__(256) void qkv_gemm(
    const float* __restrict__ x,
    const float* __restrict__ Wq,
    const float* __restrict__ Wk,
    const float* __restrict__ Wv)
{
    __shared__ float As[8][128];
    __shared__ float Bs[8][128];

    const float* W;
    float* C;
    if (blockIdx.z == 0)      { W = Wq; C = g_Q; }
    else if (blockIdx.z == 1) { W = Wk; C = g_K; }
    else                      { W = Wv; C = g_V; }

    const int tid = threadIdx.x;
    const int bn0 = blockIdx.x * 128;
    const int bm0 = blockIdx.y * 128;

    const int ar = tid >> 1, ac = (tid & 1) * 4;   // A loader: 128 rows x 8 k
    const int br = tid >> 5, bc = (tid & 31) * 4;  // B loader: 8 k x 128 cols
    const int ty = tid >> 4, tx = tid & 15;

    float acc[8][8] = {};
    const float* Aptr = x + (size_t)(bm0 + ar) * D_ + ac;
    const float* Bptr = W + (size_t)br * D_ + bn0 + bc;

    for (int k0 = 0; k0 < D_; k0 += 8) {
        float4 a = *(const float4*)(Aptr + k0);
        float4 b = *(const float4*)(Bptr + (size_t)k0 * D_);
        __syncthreads();
        As[ac + 0][ar] = a.x; As[ac + 1][ar] = a.y;
        As[ac + 2][ar] = a.z; As[ac + 3][ar] = a.w;
        *(float4*)&Bs[br][bc] = b;
        __syncthreads();
#pragma unroll
        for (int k = 0; k < 8; k++) {
            float av[8], bv[8];
            *(float4*)&av[0] = *(const float4*)&As[k][ty * 8];
            *(float4*)&av[4] = *(const float4*)&As[k][ty * 8 + 4];
            *(float4*)&bv[0] = *(const float4*)&Bs[k][tx * 8];
            *(float4*)&bv[4] = *(const float4*)&Bs[k][tx * 8 + 4];
#pragma unroll
            for (int i = 0; i < 8; i++)
#pragma unroll
                for (int j = 0; j < 8; j++)
                    acc[i][j] = fmaf(av[i], bv[j], acc[i][j]);
        }
    }

#pragma unroll
    for (int i = 0; i < 8; i++) {
        size_t orow = (size_t)(bm0 + ty * 8 + i) * D_ + bn0 + tx * 8;
        *(float4*)(C + orow)     = make_float4(acc[i][0], acc[i][1], acc[i][2], acc[i][3]);
        *(float4*)(C + orow + 4) = make_float4(acc[i][4], acc[i][5], acc[i][6], acc[i][7]);
    }
}

// ---------------------------------------------------------------------------
// Kernel 2: S = Q @ K^T (raw scores, no scale). Lower-triangular 128x128
// blocks only; diagonal blocks computed fully (softmax ignores k>q).
// ---------------------------------------------------------------------------
__global__ __launch_bounds__(256) void qk_gemm()
{
    const int kt = blockIdx.x, qt = blockIdx.y, bt = blockIdx.z;
    if (kt > qt) return;

    __shared__ float Qs[8][128];
    __shared__ float Ks[8][128];

    const float* Q  = g_Q + (size_t)bt * N_ * D_;
    const float* Km = g_K + (size_t)bt * N_ * D_;
    float* S        = g_S + (size_t)bt * N_ * N_;

    const int tid = threadIdx.x;
    const int q0 = qt * 128, k0c = kt * 128;
    const int lr = tid >> 1, lc = (tid & 1) * 4;
    const int ty = tid >> 4, tx = tid & 15;

    float acc[8][8] = {};
    const float* Qptr = Q  + (size_t)(q0  + lr) * D_ + lc;
    const float* Kptr = Km + (size_t)(k0c + lr) * D_ + lc;

    for (int d0 = 0; d0 < D_; d0 += 8) {
        float4 a = *(const float4*)(Qptr + d0);
        float4 b = *(const float4*)(Kptr + d0);
        __syncthreads();
        Qs[lc + 0][lr] = a.x; Qs[lc + 1][lr] = a.y;
        Qs[lc + 2][lr] = a.z; Qs[lc + 3][lr] = a.w;
        Ks[lc + 0][lr] = b.x; Ks[lc + 1][lr] = b.y;
        Ks[lc + 2][lr] = b.z; Ks[lc + 3][lr] = b.w;
        __syncthreads();
#pragma unroll
        for (int k = 0; k < 8; k++) {
            float av[8], bv[8];
            *(float4*)&av[0] = *(const float4*)&Qs[k][ty * 8];
            *(float4*)&av[4] = *(const float4*)&Qs[k][ty * 8 + 4];
            *(float4*)&bv[0] = *(const float4*)&Ks[k][tx * 8];
            *(float4*)&bv[4] = *(const float4*)&Ks[k][tx * 8 + 4];
#pragma unroll
            for (int i = 0; i < 8; i++)
#pragma unroll
                for (int j = 0; j < 8; j++)
                    acc[i][j] = fmaf(av[i], bv[j], acc[i][j]);
        }
    }

#pragma unroll
    for (int i = 0; i < 8; i++) {
        size_t orow = (size_t)(q0 + ty * 8 + i) * N_ + k0c + tx * 8;
        *(float4*)(S + orow)     = make_float4(acc[i][0], acc[i][1], acc[i][2], acc[i][3]);
        *(float4*)(S + orow + 4) = make_float4(acc[i][4], acc[i][5], acc[i][6], acc[i][7]);
    }
}

// ---------------------------------------------------------------------------
// Kernel 3: row-wise causal softmax of S/sqrt(D_IN), in place.
// Also zeroes k in (q, round_up(q+1,128)) so PV's diagonal tile needs no mask.
// One block of 256 threads per (b, q) row.
// ---------------------------------------------------------------------------
__global__ __launch_bounds__(256) void softmax_kernel()
{
    const int row = blockIdx.x;
    const int bt = row >> 11;        // /2048
    const int q  = row & (N_ - 1);
    float* S = g_S + (size_t)bt * N_ * N_ + (size_t)q * N_;
    const int L = q + 1;
    const int tid = threadIdx.x;
    const float scale = 0.03125f;    // 1/sqrt(1024)

    float pv[8];
    float m = -3.4e38f;
#pragma unroll
    for (int kk = 0; kk < 8; kk++) {
        int i = tid + kk * 256;
        pv[kk] = (i < L) ? S[i] : -3.4e38f;
        m = fmaxf(m, pv[kk]);
    }
#pragma unroll
    for (int off = 16; off; off >>= 1)
        m = fmaxf(m, __shfl_xor_sync(0xffffffffu, m, off));

    __shared__ float red[8];
    if ((tid & 31) == 0) red[tid >> 5] = m;
    __syncthreads();
    float mall = red[0];
#pragma unroll
    for (int j = 1; j < 8; j++) mall = fmaxf(mall, red[j]);
    __syncthreads();

    float sum = 0.f;
#pragma unroll
    for (int kk = 0; kk < 8; kk++) {
        int i = tid + kk * 256;
        if (i < L) { pv[kk] = expf((pv[kk] - mall) * scale); sum += pv[kk]; }
    }
#pragma unroll
    for (int off = 16; off; off >>= 1)
        sum += __shfl_xor_sync(0xffffffffu, sum, off);
    if ((tid & 31) == 0) red[tid >> 5] = sum;
    __syncthreads();
    float tot = 0.f;
#pragma unroll
    for (int j = 0; j < 8; j++) tot += red[j];
    const float inv = 1.0f / tot;

    const int Lpad = ((q >> 7) + 1) << 7;   // round_up(q+1, 128)
#pragma unroll
    for (int kk = 0; kk < 8; kk++) {
        int i = tid + kk * 256;
        if (i < L)         S[i] = pv[kk] * inv;
        else if (i < Lpad) S[i] = 0.f;
    }
}

// ---------------------------------------------------------------------------
// Kernel 4: context = P @ V. K-extent truncated to (qt+1)*128 (causal).
// ---------------------------------------------------------------------------
__global__ __launch_bounds__(256) void pv_gemm(float* __restrict__ out)
{
    const int et = blockIdx.x, qt = blockIdx.y, bt = blockIdx.z;

    __shared__ float Ps[8][128];
    __shared__ float Vs[8][128];

    const float* P = g_S + (size_t)bt * N_ * N_;
    const float* V = g_V + (size_t)bt * N_ * D_;

    const int tid = threadIdx.x;
    const int q0 = qt * 128, e0 = et * 128;
    const int ar = tid >> 1, ac = (tid & 1) * 4;
    const int br = tid >> 5, bc = (tid & 31) * 4;
    const int ty = tid >> 4, tx = tid & 15;

    float acc[8][8] = {};
    const int kmax = (qt + 1) * 128;
    const float* Pptr = P + (size_t)(q0 + ar) * N_ + ac;
    const float* Vptr = V + (size_t)br * D_ + e0 + bc;

    for (int k0 = 0; k0 < kmax; k0 += 8) {
        float4 a = *(const float4*)(Pptr + k0);
        float4 b = *(const float4*)(Vptr + (size_t)k0 * D_);
        __syncthreads();
        Ps[ac + 0][ar] = a.x; Ps[ac + 1][ar] = a.y;
        Ps[ac + 2][ar] = a.z; Ps[ac + 3][ar] = a.w;
        *(float4*)&Vs[br][bc] = b;
        __syncthreads();
#pragma unroll
        for (int k = 0; k < 8; k++) {
            float av[8], bv[8];
            *(float4*)&av[0] = *(const float4*)&Ps[k][ty * 8];
            *(float4*)&av[4] = *(const float4*)&Ps[k][ty * 8 + 4];
            *(float4*)&bv[0] = *(const float4*)&Vs[k][tx * 8];
            *(float4*)&bv[4] = *(const float4*)&Vs[k][tx * 8 + 4];
#pragma unroll
            for (int i = 0; i < 8; i++)
#pragma unroll
                for (int j = 0; j < 8; j++)
                    acc[i][j] = fmaf(av[i], bv[j], acc[i][j]);
        }
    }

#pragma unroll
    for (int i = 0; i < 8; i++) {
        size_t orow = ((size_t)bt * N_ + q0 + ty * 8 + i) * D_ + e0 + tx * 8;
        *(float4*)(out + orow)     = make_float4(acc[i][0], acc[i][1], acc[i][2], acc[i][3]);
        *(float4*)(out + orow + 4) = make_float4(acc[i][4], acc[i][5], acc[i][6], acc[i][7]);
    }
}

// ---------------------------------------------------------------------------
extern "C" void kernel_launch(void* const* d_in, const int* in_sizes, int n_in,
                              void* d_out, int out_size)
{
    const float* x  = (const float*)d_in[0];
    const float* Wq = (const float*)d_in[1];
    const float* Wk = (const float*)d_in[2];
    const float* Wv = (const float*)d_in[3];
    float* out = (float*)d_out;

    dim3 blk(256);
    qkv_gemm<<<dim3(D_ / 128, M_TOT / 128, 3), blk>>>(x, Wq, Wk, Wv);
    qk_gemm<<<dim3(N_ / 128, N_ / 128, B_), blk>>>();
    softmax_kernel<<<dim3(M_TOT), blk>>>();
    pv_gemm<<<dim3(D_ / 128, N_ / 128, B_), blk>>>(out);
}

// round 3
// speedup vs baseline: 2.3761x; 2.3761x over previous
#include <cuda_runtime.h>
#include <cuda_bf16.h>
#include <cstdint>

#define B_ 4
#define N_ 2048
#define D_ 1024
#define M_TOT (B_ * N_)

typedef __nv_bfloat16 bf16;

// ---------------- static device scratch ----------------
__device__ bf16  g_xh[M_TOT * D_],  g_xl[M_TOT * D_];
__device__ bf16  g_Wh[3 * D_ * D_], g_Wl[3 * D_ * D_];      // W kept [d][e] row-major
__device__ bf16  g_Qh[M_TOT * D_],  g_Ql[M_TOT * D_];
__device__ bf16  g_Kh[M_TOT * D_],  g_Kl[M_TOT * D_];
__device__ bf16  g_Vh[M_TOT * D_],  g_Vl[M_TOT * D_];       // V row-major (trans-ldmatrix)
__device__ float g_S [(size_t)B_ * N_ * N_];
__device__ bf16  g_Ph[(size_t)B_ * N_ * N_], g_Pl[(size_t)B_ * N_ * N_];

// ---------------- smem layout (double buffered) ----------------
// normal operand: 128 rows x 16 bf16, padded row stride 48B  -> 6144 B
// trans  operand: 16 rows x 128 bf16, padded row stride 272B -> 4352 B (fits 6144 slot)
static constexpr int ARR = 6144;
static constexpr int BUF = 4 * ARR;          // Ah, Al, Bh, Bl
static constexpr int SM_TOTAL = 2 * BUF;     // 49152

// ---------------- PTX helpers ----------------
__device__ __forceinline__ uint32_t smem_u32(const void* p) {
    uint32_t a;
    asm("{ .reg .u64 t; cvta.to.shared.u64 t, %1; cvt.u32.u64 %0, t; }" : "=r"(a) : "l"(p));
    return a;
}
__device__ __forceinline__ void cp16(uint32_t dst, const void* src) {
    asm volatile("cp.async.cg.shared.global [%0], [%1], 16;" :: "r"(dst), "l"(src));
}
__device__ __forceinline__ void cp_commit() { asm volatile("cp.async.commit_group;"); }
__device__ __forceinline__ void cp_wait1()  { asm volatile("cp.async.wait_group 1;"); }
__device__ __forceinline__ void cp_wait0()  { asm volatile("cp.async.wait_group 0;"); }

__device__ __forceinline__ void ldsm_x4(uint32_t r[4], uint32_t addr) {
    asm volatile("ldmatrix.sync.aligned.m8n8.x4.shared.b16 {%0,%1,%2,%3}, [%4];"
                 : "=r"(r[0]), "=r"(r[1]), "=r"(r[2]), "=r"(r[3]) : "r"(addr));
}
__device__ __forceinline__ void ldsm_x4_t(uint32_t r[4], uint32_t addr) {
    asm volatile("ldmatrix.sync.aligned.m8n8.x4.trans.shared.b16 {%0,%1,%2,%3}, [%4];"
                 : "=r"(r[0]), "=r"(r[1]), "=r"(r[2]), "=r"(r[3]) : "r"(addr));
}
__device__ __forceinline__ void mma16816(float c[4], const uint32_t a[4], const uint32_t b[2]) {
    asm volatile("mma.sync.aligned.m16n8k16.row.col.f32.bf16.bf16.f32 "
                 "{%0,%1,%2,%3}, {%4,%5,%6,%7}, {%8,%9}, {%0,%1,%2,%3};"
                 : "+f"(c[0]), "+f"(c[1]), "+f"(c[2]), "+f"(c[3])
                 : "r"(a[0]), "r"(a[1]), "r"(a[2]), "r"(a[3]), "r"(b[0]), "r"(b[1]));
}

__device__ __forceinline__ unsigned pack2(bf16 a, bf16 b) {
    __nv_bfloat162 t(a, b);
    return *reinterpret_cast<unsigned*>(&t);
}
__device__ __forceinline__ void split1(float v, bf16& h, bf16& l) {
    h = __float2bfloat16(v);
    l = __float2bfloat16(v - __bfloat162float(h));
}

// ---------------------------------------------------------------------------
// Main loop: acc(128x128) += A(128xK) * B^T, K consumed in chunks of 16.
// TRANSB=false: B given as [n][k] rows (k contiguous)  -> normal ldmatrix
// TRANSB=true : B given as [k][n] rows (n contiguous)  -> ldmatrix.trans
// Ah/Al/Bh/Bl pre-offset to the CTA tile (A rows, B rows/cols resp).
// ---------------------------------------------------------------------------
template <bool TRANSB>
__device__ __forceinline__ void mainloop(
    const bf16* __restrict__ Ah, const bf16* __restrict__ Al, int lda,
    const bf16* __restrict__ Bh, const bf16* __restrict__ Bl, int ldb,
    int nch, char* smem, float (&acc)[2][8][4])
{
    const uint32_t su = smem_u32(smem);
    const int tid = threadIdx.x;
    const int lane = tid & 31, w = tid >> 5;
    const int m0w = (w & 3) * 32, n0w = (w >> 2) * 64;

    // loader indices
    const int arow = tid >> 1, ahalf = tid & 1;        // A / B-normal
    const int tkr = tid >> 4, tseg = tid & 15;         // B-trans

    auto load_chunk = [&](int ch, int b) {
        const int k0 = ch * 16;
        const uint32_t base = su + b * BUF;
        uint32_t dA = base + arow * 48 + ahalf * 16;
        cp16(dA,        Ah + (size_t)arow * lda + k0 + ahalf * 8);
        cp16(dA + ARR,  Al + (size_t)arow * lda + k0 + ahalf * 8);
        if (!TRANSB) {
            uint32_t dB = base + 2 * ARR + arow * 48 + ahalf * 16;
            cp16(dB,       Bh + (size_t)arow * ldb + k0 + ahalf * 8);
            cp16(dB + ARR, Bl + (size_t)arow * ldb + k0 + ahalf * 8);
        } else {
            uint32_t dB = base + 2 * ARR + tkr * 272 + tseg * 16;
            cp16(dB,       Bh + (size_t)(k0 + tkr) * ldb + tseg * 8);
            cp16(dB + ARR, Bl + (size_t)(k0 + tkr) * ldb + tseg * 8);
        }
    };

    load_chunk(0, 0);
    cp_commit();

    for (int ch = 0; ch < nch; ch++) {
        if (ch + 1 < nch) {
            load_chunk(ch + 1, (ch + 1) & 1);
            cp_commit();
            cp_wait1();
        } else {
            cp_wait0();
        }
        __syncthreads();

        const uint32_t base = su + (ch & 1) * BUF;
        uint32_t Af[2][4], Alf[2][4], Bf[8][2], Blf[8][2];

        // A frags: lane addr = (m0w + mt*16 + L%16)*48 + (L/16)*16
        {
            uint32_t a0 = base + (uint32_t)((m0w + (lane & 15)) * 48 + (lane >> 4) * 16);
#pragma unroll
            for (int mt = 0; mt < 2; mt++) {
                ldsm_x4(Af[mt],  a0 + mt * 16 * 48);
                ldsm_x4(Alf[mt], a0 + mt * 16 * 48 + ARR);
            }
        }
        // B frags, 4 x4-loads covering 8 n-tiles
        if (!TRANSB) {
            uint32_t b0 = base + 2 * ARR +
                (uint32_t)((n0w + (lane & 7) + ((lane >> 4) << 3)) * 48 + ((lane >> 3) & 1) * 16);
#pragma unroll
            for (int p = 0; p < 4; p++) {
                uint32_t q[4], ql[4];
                ldsm_x4(q,  b0 + p * 16 * 48);
                ldsm_x4(ql, b0 + p * 16 * 48 + ARR);
                Bf[2*p][0] = q[0];  Bf[2*p][1] = q[1];
                Bf[2*p+1][0] = q[2]; Bf[2*p+1][1] = q[3];
                Blf[2*p][0] = ql[0]; Blf[2*p][1] = ql[1];
                Blf[2*p+1][0] = ql[2]; Blf[2*p+1][1] = ql[3];
            }
        } else {
            uint32_t b0 = base + 2 * ARR +
                (uint32_t)((lane & 15) * 272 + (lane >> 4) * 16 + n0w * 2);
#pragma unroll
            for (int p = 0; p < 4; p++) {
                uint32_t q[4], ql[4];
                ldsm_x4_t(q,  b0 + p * 16 * 2);
                ldsm_x4_t(ql, b0 + p * 16 * 2 + ARR);
                Bf[2*p][0] = q[0];  Bf[2*p][1] = q[1];
                Bf[2*p+1][0] = q[2]; Bf[2*p+1][1] = q[3];
                Blf[2*p][0] = ql[0]; Blf[2*p][1] = ql[1];
                Blf[2*p+1][0] = ql[2]; Blf[2*p+1][1] = ql[3];
            }
        }

#pragma unroll
        for (int mt = 0; mt < 2; mt++)
#pragma unroll
            for (int nt = 0; nt < 8; nt++) {
                mma16816(acc[mt][nt], Af[mt],  Bf[nt]);
                mma16816(acc[mt][nt], Af[mt],  Blf[nt]);
                mma16816(acc[mt][nt], Alf[mt], Bf[nt]);
            }
        __syncthreads();
    }
}

// ---------------- precompute: fp32 -> bf16 hi/lo splits ----------------
__global__ __launch_bounds__(256) void convert_x(const float* __restrict__ x)
{
    size_t idx = (size_t)(blockIdx.x * 256 + threadIdx.x) * 4;
    float4 v = *(const float4*)(x + idx);
    bf16 h[4], l[4];
    split1(v.x, h[0], l[0]); split1(v.y, h[1], l[1]);
    split1(v.z, h[2], l[2]); split1(v.w, h[3], l[3]);
    *(uint2*)(g_xh + idx) = make_uint2(pack2(h[0], h[1]), pack2(h[2], h[3]));
    *(uint2*)(g_xl + idx) = make_uint2(pack2(l[0], l[1]), pack2(l[2], l[3]));
}

__global__ __launch_bounds__(256) void convert_w(
    const float* __restrict__ Wq, const float* __restrict__ Wk, const float* __restrict__ Wv)
{
    const float* W = (blockIdx.z == 0) ? Wq : (blockIdx.z == 1) ? Wk : Wv;
    size_t base = (size_t)blockIdx.z * D_ * D_;
    size_t idx = (size_t)(blockIdx.x * 256 + threadIdx.x) * 4;
    float4 v = *(const float4*)(W + idx);
    bf16 h[4], l[4];
    split1(v.x, h[0], l[0]); split1(v.y, h[1], l[1]);
    split1(v.z, h[2], l[2]); split1(v.w, h[3], l[3]);
    *(uint2*)(g_Wh + base + idx) = make_uint2(pack2(h[0], h[1]), pack2(h[2], h[3]));
    *(uint2*)(g_Wl + base + idx) = make_uint2(pack2(l[0], l[1]), pack2(l[2], l[3]));
}

// ---------------- GEMM 1: Q/K/V = x @ W ----------------
__global__ __launch_bounds__(256) void qkv_mm()
{
    extern __shared__ char smem[];
    const int n0 = blockIdx.x * 128, m0 = blockIdx.y * 128, z = blockIdx.z;
    float acc[2][8][4] = {};

    mainloop<true>(g_xh + (size_t)m0 * D_, g_xl + (size_t)m0 * D_, D_,
                   g_Wh + (size_t)z * D_ * D_ + n0,
                   g_Wl + (size_t)z * D_ * D_ + n0, D_,
                   D_ / 16, smem, acc);

    bf16* Oh = (z == 0) ? g_Qh : (z == 1) ? g_Kh : g_Vh;
    bf16* Ol = (z == 0) ? g_Ql : (z == 1) ? g_Kl : g_Vl;
    const int lane = threadIdx.x & 31, w = threadIdx.x >> 5;
    const int m0w = (w & 3) * 32, n0w = (w >> 2) * 64;
#pragma unroll
    for (int mt = 0; mt < 2; mt++)
#pragma unroll
        for (int nt = 0; nt < 8; nt++) {
            int m = m0 + m0w + mt * 16 + (lane >> 2);
            int n = n0 + n0w + nt * 8 + (lane & 3) * 2;
            float* c = acc[mt][nt];
            bf16 h0, l0, h1, l1;
            split1(c[0], h0, l0); split1(c[1], h1, l1);
            *(unsigned*)(Oh + (size_t)m * D_ + n) = pack2(h0, h1);
            *(unsigned*)(Ol + (size_t)m * D_ + n) = pack2(l0, l1);
            split1(c[2], h0, l0); split1(c[3], h1, l1);
            *(unsigned*)(Oh + (size_t)(m + 8) * D_ + n) = pack2(h0, h1);
            *(unsigned*)(Ol + (size_t)(m + 8) * D_ + n) = pack2(l0, l1);
        }
}

// ---------------- GEMM 2: S = Q @ K^T (lower-tri tiles) ----------------
__global__ __launch_bounds__(256) void qk_mm()
{
    const int kt = blockIdx.x, qt = blockIdx.y, bt = blockIdx.z;
    if (kt > qt) return;
    extern __shared__ char smem[];
    float acc[2][8][4] = {};

    const size_t rb = (size_t)bt * N_ * D_;
    mainloop<false>(g_Qh + rb + (size_t)qt * 128 * D_, g_Ql + rb + (size_t)qt * 128 * D_, D_,
                    g_Kh + rb + (size_t)kt * 128 * D_, g_Kl + rb + (size_t)kt * 128 * D_, D_,
                    D_ / 16, smem, acc);

    float* S = g_S + (size_t)bt * N_ * N_;
    const int lane = threadIdx.x & 31, w = threadIdx.x >> 5;
    const int m0w = (w & 3) * 32, n0w = (w >> 2) * 64;
#pragma unroll
    for (int mt = 0; mt < 2; mt++)
#pragma unroll
        for (int nt = 0; nt < 8; nt++) {
            int q = qt * 128 + m0w + mt * 16 + (lane >> 2);
            int n = kt * 128 + n0w + nt * 8 + (lane & 3) * 2;
            float* c = acc[mt][nt];
            *(float2*)(S + (size_t)q * N_ + n)       = make_float2(c[0], c[1]);
            *(float2*)(S + (size_t)(q + 8) * N_ + n) = make_float2(c[2], c[3]);
        }
}

// ---------------- softmax -> P bf16 hi/lo (zero-padded to tile) ----------
__global__ __launch_bounds__(256) void softmax_k()
{
    const int row = blockIdx.x;
    const int bt = row >> 11;
    const int q  = row & (N_ - 1);
    const size_t base = (size_t)bt * N_ * N_ + (size_t)q * N_;
    const float* S = g_S + base;
    const int L = q + 1;
    const int tid = threadIdx.x;
    const float scale = 0.03125f;

    float pv[8];
    float m = -3.4e38f;
#pragma unroll
    for (int kk = 0; kk < 8; kk++) {
        int i = tid + kk * 256;
        pv[kk] = (i < L) ? S[i] : -3.4e38f;
        m = fmaxf(m, pv[kk]);
    }
#pragma unroll
    for (int off = 16; off; off >>= 1) m = fmaxf(m, __shfl_xor_sync(~0u, m, off));
    __shared__ float red[8];
    if ((tid & 31) == 0) red[tid >> 5] = m;
    __syncthreads();
    float mall = red[0];
#pragma unroll
    for (int j = 1; j < 8; j++) mall = fmaxf(mall, red[j]);
    __syncthreads();

    float sum = 0.f;
#pragma unroll
    for (int kk = 0; kk < 8; kk++) {
        int i = tid + kk * 256;
        if (i < L) { pv[kk] = expf((pv[kk] - mall) * scale); sum += pv[kk]; }
    }
#pragma unroll
    for (int off = 16; off; off >>= 1) sum += __shfl_xor_sync(~0u, sum, off);
    if ((tid & 31) == 0) red[tid >> 5] = sum;
    __syncthreads();
    float tot = 0.f;
#pragma unroll
    for (int j = 0; j < 8; j++) tot += red[j];
    const float inv = 1.0f / tot;

    const int Lpad = ((q >> 7) + 1) << 7;
#pragma unroll
    for (int kk = 0; kk < 8; kk++) {
        int i = tid + kk * 256;
        if (i < Lpad) {
            float p = (i < L) ? pv[kk] * inv : 0.f;
            bf16 h, l; split1(p, h, l);
            g_Ph[base + i] = h;
            g_Pl[base + i] = l;
        }
    }
}

// ---------------- GEMM 3: out = P @ V ----------------
__global__ __launch_bounds__(256) void pv_mm(float* __restrict__ out)
{
    const int et = blockIdx.x, qt = blockIdx.y, bt = blockIdx.z;
    extern __shared__ char smem[];
    float acc[2][8][4] = {};

    const size_t pb = (size_t)bt * N_ * N_ + (size_t)(qt * 128) * N_;
    const size_t vb = (size_t)bt * N_ * D_ + et * 128;
    mainloop<true>(g_Ph + pb, g_Pl + pb, N_,
                   g_Vh + vb, g_Vl + vb, D_,
                   (qt + 1) * 8, smem, acc);

    const int lane = threadIdx.x & 31, w = threadIdx.x >> 5;
    const int m0w = (w & 3) * 32, n0w = (w >> 2) * 64;
#pragma unroll
    for (int mt = 0; mt < 2; mt++)
#pragma unroll
        for (int nt = 0; nt < 8; nt++) {
            int q = qt * 128 + m0w + mt * 16 + (lane >> 2);
            int n = et * 128 + n0w + nt * 8 + (lane & 3) * 2;
            float* c = acc[mt][nt];
            float* O = out + ((size_t)bt * N_ + q) * D_ + n;
            *(float2*)O            = make_float2(c[0], c[1]);
            *(float2*)(O + 8 * D_) = make_float2(c[2], c[3]);
        }
}

// ---------------------------------------------------------------------------
extern "C" void kernel_launch(void* const* d_in, const int* in_sizes, int n_in,
                              void* d_out, int out_size)
{
    const float* x  = (const float*)d_in[0];
    const float* Wq = (const float*)d_in[1];
    const float* Wk = (const float*)d_in[2];
    const float* Wv = (const float*)d_in[3];
    float* out = (float*)d_out;

    cudaFuncSetAttribute(qkv_mm, cudaFuncAttributeMaxDynamicSharedMemorySize, SM_TOTAL);
    cudaFuncSetAttribute(qk_mm,  cudaFuncAttributeMaxDynamicSharedMemorySize, SM_TOTAL);
    cudaFuncSetAttribute(pv_mm,  cudaFuncAttributeMaxDynamicSharedMemorySize, SM_TOTAL);

    dim3 blk(256);
    convert_x<<<M_TOT * D_ / 4 / 256, blk>>>(x);
    convert_w<<<dim3(D_ * D_ / 4 / 256, 1, 3), blk>>>(Wq, Wk, Wv);
    qkv_mm<<<dim3(D_ / 128, M_TOT / 128, 3), blk, SM_TOTAL>>>();
    qk_mm<<<dim3(N_ / 128, N_ / 128, B_), blk, SM_TOTAL>>>();
    softmax_k<<<M_TOT, blk>>>();
    pv_mm<<<dim3(D_ / 128, N_ / 128, B_), blk, SM_TOTAL>>>(out);
}

// round 4
// speedup vs baseline: 2.9882x; 1.2576x over previous
#include <cuda_runtime.h>
#include <cuda_bf16.h>
#include <cstdint>

#define B_ 4
#define N_ 2048
#define D_ 1024
#define M_TOT (B_ * N_)

typedef __nv_bfloat16 bf16;

// ---------------- static device scratch ----------------
__device__ bf16  g_xh[M_TOT * D_],  g_xl[M_TOT * D_];
__device__ bf16  g_Wh[3 * D_ * D_], g_Wl[3 * D_ * D_];      // W [d][e] row-major
__device__ bf16  g_Qh[M_TOT * D_],  g_Ql[M_TOT * D_];
__device__ bf16  g_Kh[M_TOT * D_],  g_Kl[M_TOT * D_];
__device__ bf16  g_Vh[M_TOT * D_],  g_Vl[M_TOT * D_];       // V row-major (trans-ldmatrix)
__device__ float g_S [(size_t)B_ * N_ * N_];
__device__ bf16  g_Ph[(size_t)B_ * N_ * N_], g_Pl[(size_t)B_ * N_ * N_];

// ---------------- smem layout: 4-stage ring ----------------
// normal operand: 128 rows x 16 bf16, padded row stride 48B  -> 6144 B
// trans  operand: 16 rows x 128 bf16, padded row stride 272B -> 4352 B (fits slot)
static constexpr int ARR = 6144;
static constexpr int STAGE = 4 * ARR;          // Ah, Al, Bh, Bl = 24576
static constexpr int NSTAGE = 4;
static constexpr int SM_TOTAL = NSTAGE * STAGE; // 98304

// ---------------- PTX helpers ----------------
__device__ __forceinline__ uint32_t smem_u32(const void* p) {
    uint32_t a;
    asm("{ .reg .u64 t; cvta.to.shared.u64 t, %1; cvt.u32.u64 %0, t; }" : "=r"(a) : "l"(p));
    return a;
}
__device__ __forceinline__ void cp16(uint32_t dst, const void* src) {
    asm volatile("cp.async.cg.shared.global [%0], [%1], 16;" :: "r"(dst), "l"(src));
}
__device__ __forceinline__ void cp_commit() { asm volatile("cp.async.commit_group;"); }
__device__ __forceinline__ void cp_wait2()  { asm volatile("cp.async.wait_group 2;"); }

__device__ __forceinline__ void ldsm_x4(uint32_t r[4], uint32_t addr) {
    asm volatile("ldmatrix.sync.aligned.m8n8.x4.shared.b16 {%0,%1,%2,%3}, [%4];"
                 : "=r"(r[0]), "=r"(r[1]), "=r"(r[2]), "=r"(r[3]) : "r"(addr));
}
__device__ __forceinline__ void ldsm_x4_t(uint32_t r[4], uint32_t addr) {
    asm volatile("ldmatrix.sync.aligned.m8n8.x4.trans.shared.b16 {%0,%1,%2,%3}, [%4];"
                 : "=r"(r[0]), "=r"(r[1]), "=r"(r[2]), "=r"(r[3]) : "r"(addr));
}
__device__ __forceinline__ void mma16816(float c[4], const uint32_t a[4], const uint32_t b0, const uint32_t b1) {
    asm volatile("mma.sync.aligned.m16n8k16.row.col.f32.bf16.bf16.f32 "
                 "{%0,%1,%2,%3}, {%4,%5,%6,%7}, {%8,%9}, {%0,%1,%2,%3};"
                 : "+f"(c[0]), "+f"(c[1]), "+f"(c[2]), "+f"(c[3])
                 : "r"(a[0]), "r"(a[1]), "r"(a[2]), "r"(a[3]), "r"(b0), "r"(b1));
}

__device__ __forceinline__ unsigned pack2(bf16 a, bf16 b) {
    __nv_bfloat162 t(a, b);
    return *reinterpret_cast<unsigned*>(&t);
}
__device__ __forceinline__ void split1(float v, bf16& h, bf16& l) {
    h = __float2bfloat16(v);
    l = __float2bfloat16(v - __bfloat162float(h));
}

// ---------------------------------------------------------------------------
// acc(128x128) += A(128xK)*B^T, K chunks of 16, 4-stage cp.async ring.
// TRANSB=false: B as [n][k] rows; TRANSB=true: B as [k][n] rows.
// ---------------------------------------------------------------------------
template <bool TRANSB>
__device__ __forceinline__ void mainloop(
    const bf16* __restrict__ Ah, const bf16* __restrict__ Al, int lda,
    const bf16* __restrict__ Bh, const bf16* __restrict__ Bl, int ldb,
    int nch, char* smem, float (&acc)[2][8][4])
{
    const uint32_t su = smem_u32(smem);
    const int tid = threadIdx.x;
    const int lane = tid & 31, w = tid >> 5;
    const int m0w = (w & 3) * 32, n0w = (w >> 2) * 64;

    const int arow = tid >> 1, ahalf = tid & 1;        // A / B-normal loader
    const int tkr = tid >> 4, tseg = tid & 15;         // B-trans loader

    auto load_chunk = [&](int ch, int st) {
        const int k0 = ch * 16;
        const uint32_t base = su + st * STAGE;
        uint32_t dA = base + arow * 48 + ahalf * 16;
        cp16(dA,        Ah + (size_t)arow * lda + k0 + ahalf * 8);
        cp16(dA + ARR,  Al + (size_t)arow * lda + k0 + ahalf * 8);
        if (!TRANSB) {
            uint32_t dB = base + 2 * ARR + arow * 48 + ahalf * 16;
            cp16(dB,       Bh + (size_t)arow * ldb + k0 + ahalf * 8);
            cp16(dB + ARR, Bl + (size_t)arow * ldb + k0 + ahalf * 8);
        } else {
            uint32_t dB = base + 2 * ARR + tkr * 272 + tseg * 16;
            cp16(dB,       Bh + (size_t)(k0 + tkr) * ldb + tseg * 8);
            cp16(dB + ARR, Bl + (size_t)(k0 + tkr) * ldb + tseg * 8);
        }
    };

    // preload 3 stages
    for (int s = 0; s < 3; s++) {
        if (s < nch) load_chunk(s, s);
        cp_commit();
    }

    for (int ch = 0; ch < nch; ch++) {
        cp_wait2();            // groups <= ch complete
        __syncthreads();       // all warps done reading stage (ch+3)%4 (= ch-1's slot)
        if (ch + 3 < nch) load_chunk(ch + 3, (ch + 3) & 3);
        cp_commit();           // always commit (possibly empty group) to keep counting

        const uint32_t base = su + (ch & 3) * STAGE;
        uint32_t Af[2][4], Alf[2][4];
        {
            uint32_t a0 = base + (uint32_t)((m0w + (lane & 15)) * 48 + (lane >> 4) * 16);
#pragma unroll
            for (int mt = 0; mt < 2; mt++) {
                ldsm_x4(Af[mt],  a0 + mt * 16 * 48);
                ldsm_x4(Alf[mt], a0 + mt * 16 * 48 + ARR);
            }
        }
#pragma unroll
        for (int p = 0; p < 4; p++) {
            uint32_t q[4], ql[4];
            if (!TRANSB) {
                uint32_t b0 = base + 2 * ARR +
                    (uint32_t)((n0w + (lane & 7) + ((lane >> 4) << 3)) * 48 + ((lane >> 3) & 1) * 16)
                    + p * 16 * 48;
                ldsm_x4(q,  b0);
                ldsm_x4(ql, b0 + ARR);
            } else {
                uint32_t b0 = base + 2 * ARR +
                    (uint32_t)((lane & 15) * 272 + (lane >> 4) * 16 + n0w * 2)
                    + p * 16 * 2;
                ldsm_x4_t(q,  b0);
                ldsm_x4_t(ql, b0 + ARR);
            }
            const int nt0 = 2 * p, nt1 = 2 * p + 1;
#pragma unroll
            for (int mt = 0; mt < 2; mt++) {
                mma16816(acc[mt][nt0], Af[mt],  q[0],  q[1]);
                mma16816(acc[mt][nt0], Af[mt],  ql[0], ql[1]);
                mma16816(acc[mt][nt0], Alf[mt], q[0],  q[1]);
                mma16816(acc[mt][nt1], Af[mt],  q[2],  q[3]);
                mma16816(acc[mt][nt1], Af[mt],  ql[2], ql[3]);
                mma16816(acc[mt][nt1], Alf[mt], q[2],  q[3]);
            }
        }
    }
    __syncthreads();
}

// ---------------- precompute: fp32 -> bf16 hi/lo splits ----------------
__global__ __launch_bounds__(256) void convert_x(const float* __restrict__ x)
{
    size_t idx = (size_t)(blockIdx.x * 256 + threadIdx.x) * 4;
    float4 v = *(const float4*)(x + idx);
    bf16 h[4], l[4];
    split1(v.x, h[0], l[0]); split1(v.y, h[1], l[1]);
    split1(v.z, h[2], l[2]); split1(v.w, h[3], l[3]);
    *(uint2*)(g_xh + idx) = make_uint2(pack2(h[0], h[1]), pack2(h[2], h[3]));
    *(uint2*)(g_xl + idx) = make_uint2(pack2(l[0], l[1]), pack2(l[2], l[3]));
}

__global__ __launch_bounds__(256) void convert_w(
    const float* __restrict__ Wq, const float* __restrict__ Wk, const float* __restrict__ Wv)
{
    const float* W = (blockIdx.z == 0) ? Wq : (blockIdx.z == 1) ? Wk : Wv;
    size_t base = (size_t)blockIdx.z * D_ * D_;
    size_t idx = (size_t)(blockIdx.x * 256 + threadIdx.x) * 4;
    float4 v = *(const float4*)(W + idx);
    bf16 h[4], l[4];
    split1(v.x, h[0], l[0]); split1(v.y, h[1], l[1]);
    split1(v.z, h[2], l[2]); split1(v.w, h[3], l[3]);
    *(uint2*)(g_Wh + base + idx) = make_uint2(pack2(h[0], h[1]), pack2(h[2], h[3]));
    *(uint2*)(g_Wl + base + idx) = make_uint2(pack2(l[0], l[1]), pack2(l[2], l[3]));
}

// ---------------- GEMM 1: Q/K/V = x @ W ----------------
__global__ __launch_bounds__(256, 2) void qkv_mm()
{
    extern __shared__ char smem[];
    const int n0 = blockIdx.x * 128, m0 = blockIdx.y * 128, z = blockIdx.z;
    float acc[2][8][4] = {};

    mainloop<true>(g_xh + (size_t)m0 * D_, g_xl + (size_t)m0 * D_, D_,
                   g_Wh + (size_t)z * D_ * D_ + n0,
                   g_Wl + (size_t)z * D_ * D_ + n0, D_,
                   D_ / 16, smem, acc);

    bf16* Oh = (z == 0) ? g_Qh : (z == 1) ? g_Kh : g_Vh;
    bf16* Ol = (z == 0) ? g_Ql : (z == 1) ? g_Kl : g_Vl;
    const int lane = threadIdx.x & 31, w = threadIdx.x >> 5;
    const int m0w = (w & 3) * 32, n0w = (w >> 2) * 64;
#pragma unroll
    for (int mt = 0; mt < 2; mt++)
#pragma unroll
        for (int nt = 0; nt < 8; nt++) {
            int m = m0 + m0w + mt * 16 + (lane >> 2);
            int n = n0 + n0w + nt * 8 + (lane & 3) * 2;
            float* c = acc[mt][nt];
            bf16 h0, l0, h1, l1;
            split1(c[0], h0, l0); split1(c[1], h1, l1);
            *(unsigned*)(Oh + (size_t)m * D_ + n) = pack2(h0, h1);
            *(unsigned*)(Ol + (size_t)m * D_ + n) = pack2(l0, l1);
            split1(c[2], h0, l0); split1(c[3], h1, l1);
            *(unsigned*)(Oh + (size_t)(m + 8) * D_ + n) = pack2(h0, h1);
            *(unsigned*)(Ol + (size_t)(m + 8) * D_ + n) = pack2(l0, l1);
        }
}

// ---------------- GEMM 2: S = Q @ K^T (lower-tri tiles) ----------------
__global__ __launch_bounds__(256, 2) void qk_mm()
{
    const int kt = blockIdx.x, qt = blockIdx.y, bt = blockIdx.z;
    if (kt > qt) return;
    extern __shared__ char smem[];
    float acc[2][8][4] = {};

    const size_t rb = (size_t)bt * N_ * D_;
    mainloop<false>(g_Qh + rb + (size_t)qt * 128 * D_, g_Ql + rb + (size_t)qt * 128 * D_, D_,
                    g_Kh + rb + (size_t)kt * 128 * D_, g_Kl + rb + (size_t)kt * 128 * D_, D_,
                    D_ / 16, smem, acc);

    float* S = g_S + (size_t)bt * N_ * N_;
    const int lane = threadIdx.x & 31, w = threadIdx.x >> 5;
    const int m0w = (w & 3) * 32, n0w = (w >> 2) * 64;
#pragma unroll
    for (int mt = 0; mt < 2; mt++)
#pragma unroll
        for (int nt = 0; nt < 8; nt++) {
            int q = qt * 128 + m0w + mt * 16 + (lane >> 2);
            int n = kt * 128 + n0w + nt * 8 + (lane & 3) * 2;
            float* c = acc[mt][nt];
            *(float2*)(S + (size_t)q * N_ + n)       = make_float2(c[0], c[1]);
            *(float2*)(S + (size_t)(q + 8) * N_ + n) = make_float2(c[2], c[3]);
        }
}

// ---------------- softmax -> P bf16 hi/lo (zero-padded to tile) ----------
__global__ __launch_bounds__(256) void softmax_k()
{
    const int row = blockIdx.x;
    const int bt = row >> 11;
    const int q  = row & (N_ - 1);
    const size_t base = (size_t)bt * N_ * N_ + (size_t)q * N_;
    const float* S = g_S + base;
    const int L = q + 1;
    const int tid = threadIdx.x;
    const float scale = 0.03125f;

    float pv[8];
    float m = -3.4e38f;
#pragma unroll
    for (int kk = 0; kk < 8; kk++) {
        int i = tid + kk * 256;
        pv[kk] = (i < L) ? S[i] : -3.4e38f;
        m = fmaxf(m, pv[kk]);
    }
#pragma unroll
    for (int off = 16; off; off >>= 1) m = fmaxf(m, __shfl_xor_sync(~0u, m, off));
    __shared__ float red[8];
    if ((tid & 31) == 0) red[tid >> 5] = m;
    __syncthreads();
    float mall = red[0];
#pragma unroll
    for (int j = 1; j < 8; j++) mall = fmaxf(mall, red[j]);
    __syncthreads();

    float sum = 0.f;
#pragma unroll
    for (int kk = 0; kk < 8; kk++) {
        int i = tid + kk * 256;
        if (i < L) { pv[kk] = expf((pv[kk] - mall) * scale); sum += pv[kk]; }
    }
#pragma unroll
    for (int off = 16; off; off >>= 1) sum += __shfl_xor_sync(~0u, sum, off);
    if ((tid & 31) == 0) red[tid >> 5] = sum;
    __syncthreads();
    float tot = 0.f;
#pragma unroll
    for (int j = 0; j < 8; j++) tot += red[j];
    const float inv = 1.0f / tot;

    const int Lpad = ((q >> 7) + 1) << 7;
#pragma unroll
    for (int kk = 0; kk < 8; kk++) {
        int i = tid + kk * 256;
        if (i < Lpad) {
            float p = (i < L) ? pv[kk] * inv : 0.f;
            bf16 h, l; split1(p, h, l);
            g_Ph[base + i] = h;
            g_Pl[base + i] = l;
        }
    }
}

// ---------------- GEMM 3: out = P @ V ----------------
__global__ __launch_bounds__(256, 2) void pv_mm(float* __restrict__ out)
{
    const int et = blockIdx.x, qt = blockIdx.y, bt = blockIdx.z;
    extern __shared__ char smem[];
    float acc[2][8][4] = {};

    const size_t pb = (size_t)bt * N_ * N_ + (size_t)(qt * 128) * N_;
    const size_t vb = (size_t)bt * N_ * D_ + et * 128;
    mainloop<true>(g_Ph + pb, g_Pl + pb, N_,
                   g_Vh + vb, g_Vl + vb, D_,
                   (qt + 1) * 8, smem, acc);

    const int lane = threadIdx.x & 31, w = threadIdx.x >> 5;
    const int m0w = (w & 3) * 32, n0w = (w >> 2) * 64;
#pragma unroll
    for (int mt = 0; mt < 2; mt++)
#pragma unroll
        for (int nt = 0; nt < 8; nt++) {
            int q = qt * 128 + m0w + mt * 16 + (lane >> 2);
            int n = et * 128 + n0w + nt * 8 + (lane & 3) * 2;
            float* c = acc[mt][nt];
            float* O = out + ((size_t)bt * N_ + q) * D_ + n;
            *(float2*)O            = make_float2(c[0], c[1]);
            *(float2*)(O + 8 * D_) = make_float2(c[2], c[3]);
        }
}

// ---------------------------------------------------------------------------
extern "C" void kernel_launch(void* const* d_in, const int* in_sizes, int n_in,
                              void* d_out, int out_size)
{
    const float* x  = (const float*)d_in[0];
    const float* Wq = (const float*)d_in[1];
    const float* Wk = (const float*)d_in[2];
    const float* Wv = (const float*)d_in[3];
    float* out = (float*)d_out;

    cudaFuncSetAttribute(qkv_mm, cudaFuncAttributeMaxDynamicSharedMemorySize, SM_TOTAL);
    cudaFuncSetAttribute(qk_mm,  cudaFuncAttributeMaxDynamicSharedMemorySize, SM_TOTAL);
    cudaFuncSetAttribute(pv_mm,  cudaFuncAttributeMaxDynamicSharedMemorySize, SM_TOTAL);

    dim3 blk(256);
    convert_x<<<M_TOT * D_ / 4 / 256, blk>>>(x);
    convert_w<<<dim3(D_ * D_ / 4 / 256, 1, 3), blk>>>(Wq, Wk, Wv);
    qkv_mm<<<dim3(D_ / 128, M_TOT / 128, 3), blk, SM_TOTAL>>>();
    qk_mm<<<dim3(N_ / 128, N_ / 128, B_), blk, SM_TOTAL>>>();
    softmax_k<<<M_TOT, blk>>>();
    pv_mm<<<dim3(D_ / 128, N_ / 128, B_), blk, SM_TOTAL>>>(out);
}

// round 5
// speedup vs baseline: 3.0102x; 1.0074x over previous
#include <cuda_runtime.h>
#include <cuda_bf16.h>
#include <cstdint>

#define B_ 4
#define N_ 2048
#define D_ 1024
#define M_TOT (B_ * N_)

typedef __nv_bfloat16 bf16;

// ---------------- static device scratch ----------------
__device__ bf16  g_xh[M_TOT * D_],  g_xl[M_TOT * D_];
__device__ bf16  g_Wh[3 * D_ * D_], g_Wl[3 * D_ * D_];      // W [d][e] row-major
__device__ bf16  g_Qh[M_TOT * D_],  g_Ql[M_TOT * D_];
__device__ bf16  g_Kh[M_TOT * D_],  g_Kl[M_TOT * D_];
__device__ bf16  g_Vh[M_TOT * D_],  g_Vl[M_TOT * D_];       // V row-major (trans-ldmatrix)
__device__ float g_S [(size_t)B_ * N_ * N_];
__device__ bf16  g_Ph[(size_t)B_ * N_ * N_], g_Pl[(size_t)B_ * N_ * N_];

// ---------------- smem: 3-stage ring, K-chunk = 32 ----------------
// normal operand array: 128 rows x 64B, XOR swizzle  -> 8192 B exact
// trans  operand array:  32 rows x 256B, XOR swizzle -> 8192 B exact
static constexpr int ARR = 8192;
static constexpr int STAGE = 4 * ARR;            // Ah, Al, Bh, Bl = 32768
static constexpr int NSTAGE = 3;
static constexpr int SM_TOTAL = NSTAGE * STAGE;  // 98304

// swizzles: keep 16B alignment; give 8 distinct 16B banks per 8-row group
__device__ __forceinline__ uint32_t swzN(uint32_t r, uint32_t c) {   // 64B rows
    return r * 64u + (c ^ ((r & 6u) << 3));
}
__device__ __forceinline__ uint32_t swzT(uint32_t r, uint32_t c) {   // 256B rows
    return r * 256u + (c ^ ((r & 7u) << 4));
}

// ---------------- PTX helpers ----------------
__device__ __forceinline__ uint32_t smem_u32(const void* p) {
    uint32_t a;
    asm("{ .reg .u64 t; cvta.to.shared.u64 t, %1; cvt.u32.u64 %0, t; }" : "=r"(a) : "l"(p));
    return a;
}
__device__ __forceinline__ void cp16(uint32_t dst, const void* src) {
    asm volatile("cp.async.cg.shared.global [%0], [%1], 16;" :: "r"(dst), "l"(src));
}
__device__ __forceinline__ void cp_commit() { asm volatile("cp.async.commit_group;"); }
__device__ __forceinline__ void cp_wait1()  { asm volatile("cp.async.wait_group 1;"); }

__device__ __forceinline__ void ldsm_x4(uint32_t r[4], uint32_t addr) {
    asm volatile("ldmatrix.sync.aligned.m8n8.x4.shared.b16 {%0,%1,%2,%3}, [%4];"
                 : "=r"(r[0]), "=r"(r[1]), "=r"(r[2]), "=r"(r[3]) : "r"(addr));
}
__device__ __forceinline__ void ldsm_x4_t(uint32_t r[4], uint32_t addr) {
    asm volatile("ldmatrix.sync.aligned.m8n8.x4.trans.shared.b16 {%0,%1,%2,%3}, [%4];"
                 : "=r"(r[0]), "=r"(r[1]), "=r"(r[2]), "=r"(r[3]) : "r"(addr));
}
__device__ __forceinline__ void mma16816(float c[4], const uint32_t a[4], uint32_t b0, uint32_t b1) {
    asm volatile("mma.sync.aligned.m16n8k16.row.col.f32.bf16.bf16.f32 "
                 "{%0,%1,%2,%3}, {%4,%5,%6,%7}, {%8,%9}, {%0,%1,%2,%3};"
                 : "+f"(c[0]), "+f"(c[1]), "+f"(c[2]), "+f"(c[3])
                 : "r"(a[0]), "r"(a[1]), "r"(a[2]), "r"(a[3]), "r"(b0), "r"(b1));
}

__device__ __forceinline__ unsigned pack2(bf16 a, bf16 b) {
    __nv_bfloat162 t(a, b);
    return *reinterpret_cast<unsigned*>(&t);
}
__device__ __forceinline__ void split1(float v, bf16& h, bf16& l) {
    h = __float2bfloat16(v);
    l = __float2bfloat16(v - __bfloat162float(h));
}

// ---------------------------------------------------------------------------
// acc(128x128) += A(128xK)*B^T, K chunks of 32, 3-stage cp.async ring,
// ONE __syncthreads per chunk.
// TRANSB=false: B as [n][k] rows; TRANSB=true: B as [k][n] rows.
// ---------------------------------------------------------------------------
template <bool TRANSB>
__device__ __forceinline__ void mainloop(
    const bf16* __restrict__ Ah, const bf16* __restrict__ Al, int lda,
    const bf16* __restrict__ Bh, const bf16* __restrict__ Bl, int ldb,
    int nch, char* smem, float (&acc)[2][8][4])
{
    const uint32_t su = smem_u32(smem);
    const int tid = threadIdx.x;
    const int lane = tid & 31, w = tid >> 5;
    const int m0w = (w & 3) * 32, n0w = (w >> 2) * 64;

    // loader indices (per thread: 2x cp16 per array)
    const int arow = tid >> 1;                       // normal arrays: row, 2 x 16B
    const int ac0  = (tid & 1) * 32;
    const int tkr = tid >> 4, tseg = tid & 15;       // trans arrays

    auto load_chunk = [&](int ch, int st) {
        const int k0 = ch * 32;
        const uint32_t base = su + st * STAGE;
        // A hi/lo: rows 0..127, 64B each
        const bf16* pAh = Ah + (size_t)arow * lda + k0 + (ac0 >> 1);
        const bf16* pAl = Al + (size_t)arow * lda + k0 + (ac0 >> 1);
        uint32_t d0 = base + swzN(arow, ac0);
        uint32_t d1 = base + swzN(arow, ac0 + 16);
        cp16(d0, pAh);            cp16(d1, pAh + 8);
        cp16(d0 + ARR, pAl);      cp16(d1 + ARR, pAl + 8);
        if (!TRANSB) {
            const bf16* pBh = Bh + (size_t)arow * ldb + k0 + (ac0 >> 1);
            const bf16* pBl = Bl + (size_t)arow * ldb + k0 + (ac0 >> 1);
            uint32_t e0 = base + 2 * ARR + swzN(arow, ac0);
            uint32_t e1 = base + 2 * ARR + swzN(arow, ac0 + 16);
            cp16(e0, pBh);        cp16(e1, pBh + 8);
            cp16(e0 + ARR, pBl);  cp16(e1 + ARR, pBl + 8);
        } else {
            // 32 k-rows x 256B; thread covers rows tkr and tkr+16
            const bf16* pBh0 = Bh + (size_t)(k0 + tkr) * ldb + tseg * 8;
            const bf16* pBl0 = Bl + (size_t)(k0 + tkr) * ldb + tseg * 8;
            const bf16* pBh1 = Bh + (size_t)(k0 + tkr + 16) * ldb + tseg * 8;
            const bf16* pBl1 = Bl + (size_t)(k0 + tkr + 16) * ldb + tseg * 8;
            uint32_t e0 = base + 2 * ARR + swzT(tkr, tseg * 16);
            uint32_t e1 = base + 2 * ARR + swzT(tkr + 16, tseg * 16);
            cp16(e0, pBh0);       cp16(e0 + ARR, pBl0);
            cp16(e1, pBh1);       cp16(e1 + ARR, pBl1);
        }
    };

    // preload 2 chunks
    load_chunk(0, 0); cp_commit();
    if (nch > 1) load_chunk(1, 1);
    cp_commit();

    for (int ch = 0; ch < nch; ch++) {
        cp_wait1();            // group ch complete (ch+1 may be in flight)
        __syncthreads();       // data visible; everyone done computing ch-1
        if (ch + 2 < nch) load_chunk(ch + 2, (ch + 2) % 3);
        cp_commit();           // always commit to keep group counting uniform

        const uint32_t base = su + (ch % 3) * STAGE;
#pragma unroll
        for (int kk = 0; kk < 2; kk++) {           // two k16 halves of the 32-chunk
            uint32_t Af[2][4], Alf[2][4];
            {
                const uint32_t r0 = m0w + (lane & 15);
                const uint32_t c0 = (lane >> 4) * 16 + kk * 32;
#pragma unroll
                for (int mt = 0; mt < 2; mt++) {
                    uint32_t a0 = base + swzN(r0 + mt * 16, c0);
                    ldsm_x4(Af[mt],  a0);
                    ldsm_x4(Alf[mt], a0 + ARR);
                }
            }
#pragma unroll
            for (int p = 0; p < 4; p++) {
                uint32_t q[4], ql[4];
                if (!TRANSB) {
                    const uint32_t r0 = n0w + (lane & 7) + ((lane >> 4) << 3) + p * 16;
                    const uint32_t c0 = ((lane >> 3) & 1) * 16 + kk * 32;
                    uint32_t b0 = base + 2 * ARR + swzN(r0, c0);
                    ldsm_x4(q,  b0);
                    ldsm_x4(ql, b0 + ARR);
                } else {
                    const uint32_t r0 = (lane & 15) + kk * 16;
                    const uint32_t c0 = (lane >> 4) * 16 + n0w * 2 + p * 32;
                    uint32_t b0 = base + 2 * ARR + swzT(r0, c0);
                    ldsm_x4_t(q,  b0);
                    ldsm_x4_t(ql, b0 + ARR);
                }
                const int nt0 = 2 * p, nt1 = 2 * p + 1;
#pragma unroll
                for (int mt = 0; mt < 2; mt++) {
                    mma16816(acc[mt][nt0], Af[mt],  q[0],  q[1]);
                    mma16816(acc[mt][nt0], Af[mt],  ql[0], ql[1]);
                    mma16816(acc[mt][nt0], Alf[mt], q[0],  q[1]);
                    mma16816(acc[mt][nt1], Af[mt],  q[2],  q[3]);
                    mma16816(acc[mt][nt1], Af[mt],  ql[2], ql[3]);
                    mma16816(acc[mt][nt1], Alf[mt], q[2],  q[3]);
                }
            }
        }
    }
    __syncthreads();
}

// ---------------- precompute: fp32 -> bf16 hi/lo splits ----------------
__global__ __launch_bounds__(256) void convert_x(const float* __restrict__ x)
{
    size_t idx = (size_t)(blockIdx.x * 256 + threadIdx.x) * 4;
    float4 v = *(const float4*)(x + idx);
    bf16 h[4], l[4];
    split1(v.x, h[0], l[0]); split1(v.y, h[1], l[1]);
    split1(v.z, h[2], l[2]); split1(v.w, h[3], l[3]);
    *(uint2*)(g_xh + idx) = make_uint2(pack2(h[0], h[1]), pack2(h[2], h[3]));
    *(uint2*)(g_xl + idx) = make_uint2(pack2(l[0], l[1]), pack2(l[2], l[3]));
}

__global__ __launch_bounds__(256) void convert_w(
    const float* __restrict__ Wq, const float* __restrict__ Wk, const float* __restrict__ Wv)
{
    const float* W = (blockIdx.z == 0) ? Wq : (blockIdx.z == 1) ? Wk : Wv;
    size_t base = (size_t)blockIdx.z * D_ * D_;
    size_t idx = (size_t)(blockIdx.x * 256 + threadIdx.x) * 4;
    float4 v = *(const float4*)(W + idx);
    bf16 h[4], l[4];
    split1(v.x, h[0], l[0]); split1(v.y, h[1], l[1]);
    split1(v.z, h[2], l[2]); split1(v.w, h[3], l[3]);
    *(uint2*)(g_Wh + base + idx) = make_uint2(pack2(h[0], h[1]), pack2(h[2], h[3]));
    *(uint2*)(g_Wl + base + idx) = make_uint2(pack2(l[0], l[1]), pack2(l[2], l[3]));
}

// ---------------- GEMM 1: Q/K/V = x @ W ----------------
__global__ __launch_bounds__(256, 2) void qkv_mm()
{
    extern __shared__ char smem[];
    const int n0 = blockIdx.x * 128, m0 = blockIdx.y * 128, z = blockIdx.z;
    float acc[2][8][4] = {};

    mainloop<true>(g_xh + (size_t)m0 * D_, g_xl + (size_t)m0 * D_, D_,
                   g_Wh + (size_t)z * D_ * D_ + n0,
                   g_Wl + (size_t)z * D_ * D_ + n0, D_,
                   D_ / 32, smem, acc);

    bf16* Oh = (z == 0) ? g_Qh : (z == 1) ? g_Kh : g_Vh;
    bf16* Ol = (z == 0) ? g_Ql : (z == 1) ? g_Kl : g_Vl;
    const int lane = threadIdx.x & 31, w = threadIdx.x >> 5;
    const int m0w = (w & 3) * 32, n0w = (w >> 2) * 64;
#pragma unroll
    for (int mt = 0; mt < 2; mt++)
#pragma unroll
        for (int nt = 0; nt < 8; nt++) {
            int m = m0 + m0w + mt * 16 + (lane >> 2);
            int n = n0 + n0w + nt * 8 + (lane & 3) * 2;
            float* c = acc[mt][nt];
            bf16 h0, l0, h1, l1;
            split1(c[0], h0, l0); split1(c[1], h1, l1);
            *(unsigned*)(Oh + (size_t)m * D_ + n) = pack2(h0, h1);
            *(unsigned*)(Ol + (size_t)m * D_ + n) = pack2(l0, l1);
            split1(c[2], h0, l0); split1(c[3], h1, l1);
            *(unsigned*)(Oh + (size_t)(m + 8) * D_ + n) = pack2(h0, h1);
            *(unsigned*)(Ol + (size_t)(m + 8) * D_ + n) = pack2(l0, l1);
        }
}

// ---------------- GEMM 2: S = Q @ K^T (compact triangular grid) ----------
__global__ __launch_bounds__(256, 2) void qk_mm()
{
    const int i = blockIdx.x, bt = blockIdx.z;
    int qt = (int)((sqrtf(8.0f * i + 1.0f) - 1.0f) * 0.5f);
    while ((qt + 1) * (qt + 2) / 2 <= i) qt++;
    while (qt * (qt + 1) / 2 > i) qt--;
    const int kt = i - qt * (qt + 1) / 2;

    extern __shared__ char smem[];
    float acc[2][8][4] = {};

    const size_t rb = (size_t)bt * N_ * D_;
    mainloop<false>(g_Qh + rb + (size_t)qt * 128 * D_, g_Ql + rb + (size_t)qt * 128 * D_, D_,
                    g_Kh + rb + (size_t)kt * 128 * D_, g_Kl + rb + (size_t)kt * 128 * D_, D_,
                    D_ / 32, smem, acc);

    float* S = g_S + (size_t)bt * N_ * N_;
    const int lane = threadIdx.x & 31, w = threadIdx.x >> 5;
    const int m0w = (w & 3) * 32, n0w = (w >> 2) * 64;
#pragma unroll
    for (int mt = 0; mt < 2; mt++)
#pragma unroll
        for (int nt = 0; nt < 8; nt++) {
            int q = qt * 128 + m0w + mt * 16 + (lane >> 2);
            int n = kt * 128 + n0w + nt * 8 + (lane & 3) * 2;
            float* c = acc[mt][nt];
            *(float2*)(S + (size_t)q * N_ + n)       = make_float2(c[0], c[1]);
            *(float2*)(S + (size_t)(q + 8) * N_ + n) = make_float2(c[2], c[3]);
        }
}

// ---------------- softmax -> P bf16 hi/lo (zero-padded to tile) ----------
__global__ __launch_bounds__(256) void softmax_k()
{
    const int row = blockIdx.x;
    const int bt = row >> 11;
    const int q  = row & (N_ - 1);
    const size_t base = (size_t)bt * N_ * N_ + (size_t)q * N_;
    const float* S = g_S + base;
    const int L = q + 1;
    const int tid = threadIdx.x;
    const float scale = 0.03125f;

    float pv[8];
    float m = -3.4e38f;
#pragma unroll
    for (int kk = 0; kk < 8; kk++) {
        int i = tid + kk * 256;
        pv[kk] = (i < L) ? S[i] : -3.4e38f;
        m = fmaxf(m, pv[kk]);
    }
#pragma unroll
    for (int off = 16; off; off >>= 1) m = fmaxf(m, __shfl_xor_sync(~0u, m, off));
    __shared__ float red[8];
    if ((tid & 31) == 0) red[tid >> 5] = m;
    __syncthreads();
    float mall = red[0];
#pragma unroll
    for (int j = 1; j < 8; j++) mall = fmaxf(mall, red[j]);
    __syncthreads();

    float sum = 0.f;
#pragma unroll
    for (int kk = 0; kk < 8; kk++) {
        int i = tid + kk * 256;
        if (i < L) { pv[kk] = expf((pv[kk] - mall) * scale); sum += pv[kk]; }
    }
#pragma unroll
    for (int off = 16; off; off >>= 1) sum += __shfl_xor_sync(~0u, sum, off);
    if ((tid & 31) == 0) red[tid >> 5] = sum;
    __syncthreads();
    float tot = 0.f;
#pragma unroll
    for (int j = 0; j < 8; j++) tot += red[j];
    const float inv = 1.0f / tot;

    const int Lpad = ((q >> 7) + 1) << 7;
#pragma unroll
    for (int kk = 0; kk < 8; kk++) {
        int i = tid + kk * 256;
        if (i < Lpad) {
            float p = (i < L) ? pv[kk] * inv : 0.f;
            bf16 h, l; split1(p, h, l);
            g_Ph[base + i] = h;
            g_Pl[base + i] = l;
        }
    }
}

// ---------------- GEMM 3: out = P @ V (heavy tiles first) ----------------
__global__ __launch_bounds__(256, 2) void pv_mm(float* __restrict__ out)
{
    const int et = blockIdx.x, qt = (N_ / 128 - 1) - blockIdx.y, bt = blockIdx.z;
    extern __shared__ char smem[];
    float acc[2][8][4] = {};

    const size_t pb = (size_t)bt * N_ * N_ + (size_t)(qt * 128) * N_;
    const size_t vb = (size_t)bt * N_ * D_ + et * 128;
    mainloop<true>(g_Ph + pb, g_Pl + pb, N_,
                   g_Vh + vb, g_Vl + vb, D_,
                   (qt + 1) * 4, smem, acc);

    const int lane = threadIdx.x & 31, w = threadIdx.x >> 5;
    const int m0w = (w & 3) * 32, n0w = (w >> 2) * 64;
#pragma unroll
    for (int mt = 0; mt < 2; mt++)
#pragma unroll
        for (int nt = 0; nt < 8; nt++) {
            int q = qt * 128 + m0w + mt * 16 + (lane >> 2);
            int n = et * 128 + n0w + nt * 8 + (lane & 3) * 2;
            float* c = acc[mt][nt];
            float* O = out + ((size_t)bt * N_ + q) * D_ + n;
            *(float2*)O            = make_float2(c[0], c[1]);
            *(float2*)(O + 8 * D_) = make_float2(c[2], c[3]);
        }
}

// ---------------------------------------------------------------------------
extern "C" void kernel_launch(void* const* d_in, const int* in_sizes, int n_in,
                              void* d_out, int out_size)
{
    const float* x  = (const float*)d_in[0];
    const float* Wq = (const float*)d_in[1];
    const float* Wk = (const float*)d_in[2];
    const float* Wv = (const float*)d_in[3];
    float* out = (float*)d_out;

    cudaFuncSetAttribute(qkv_mm, cudaFuncAttributeMaxDynamicSharedMemorySize, SM_TOTAL);
    cudaFuncSetAttribute(qk_mm,  cudaFuncAttributeMaxDynamicSharedMemorySize, SM_TOTAL);
    cudaFuncSetAttribute(pv_mm,  cudaFuncAttributeMaxDynamicSharedMemorySize, SM_TOTAL);

    const int NT = N_ / 128;                       // 16
    const int NTRI = NT * (NT + 1) / 2;            // 136

    dim3 blk(256);
    convert_x<<<M_TOT * D_ / 4 / 256, blk>>>(x);
    convert_w<<<dim3(D_ * D_ / 4 / 256, 1, 3), blk>>>(Wq, Wk, Wv);
    qkv_mm<<<dim3(D_ / 128, M_TOT / 128, 3), blk, SM_TOTAL>>>();
    qk_mm<<<dim3(NTRI, 1, B_), blk, SM_TOTAL>>>();
    softmax_k<<<M_TOT, blk>>>();
    pv_mm<<<dim3(D_ / 128, NT, B_), blk, SM_TOTAL>>>(out);
}

// round 6
// speedup vs baseline: 3.0399x; 1.0099x over previous
#include <cuda_runtime.h>
#include <cuda_bf16.h>
#include <cstdint>

#define B_ 4
#define N_ 2048
#define D_ 1024
#define M_TOT (B_ * N_)

typedef __nv_bfloat16 bf16;

// ---------------- static device scratch ----------------
__device__ bf16  g_xh[M_TOT * D_],  g_xl[M_TOT * D_];
__device__ bf16  g_Wh[3 * D_ * D_], g_Wl[3 * D_ * D_];      // W [d][e] row-major
__device__ bf16  g_Qh[M_TOT * D_],  g_Ql[M_TOT * D_];
__device__ bf16  g_Kh[M_TOT * D_],  g_Kl[M_TOT * D_];
__device__ bf16  g_Vh[M_TOT * D_],  g_Vl[M_TOT * D_];       // V row-major (trans-ldmatrix)
__device__ float g_S [(size_t)B_ * N_ * N_];
__device__ bf16  g_Ph[(size_t)B_ * N_ * N_], g_Pl[(size_t)B_ * N_ * N_];

// ---------------- smem: 3-stage ring, K-chunk = 32 ----------------
static constexpr int ARR = 8192;
static constexpr int STAGE = 4 * ARR;            // Ah, Al, Bh, Bl = 32768
static constexpr int NSTAGE = 3;
static constexpr int SM_TOTAL = NSTAGE * STAGE;  // 98304

__device__ __forceinline__ uint32_t swzN(uint32_t r, uint32_t c) {   // 64B rows
    return r * 64u + (c ^ ((r & 6u) << 3));
}
__device__ __forceinline__ uint32_t swzT(uint32_t r, uint32_t c) {   // 256B rows
    return r * 256u + (c ^ ((r & 7u) << 4));
}

// ---------------- PTX helpers ----------------
__device__ __forceinline__ uint32_t smem_u32(const void* p) {
    uint32_t a;
    asm("{ .reg .u64 t; cvta.to.shared.u64 t, %1; cvt.u32.u64 %0, t; }" : "=r"(a) : "l"(p));
    return a;
}
__device__ __forceinline__ void cp16(uint32_t dst, const void* src) {
    asm volatile("cp.async.cg.shared.global [%0], [%1], 16;" :: "r"(dst), "l"(src));
}
__device__ __forceinline__ void cp_commit() { asm volatile("cp.async.commit_group;"); }
__device__ __forceinline__ void cp_wait1()  { asm volatile("cp.async.wait_group 1;"); }

__device__ __forceinline__ void ldsm_x4(uint32_t r[4], uint32_t addr) {
    asm volatile("ldmatrix.sync.aligned.m8n8.x4.shared.b16 {%0,%1,%2,%3}, [%4];"
                 : "=r"(r[0]), "=r"(r[1]), "=r"(r[2]), "=r"(r[3]) : "r"(addr));
}
__device__ __forceinline__ void ldsm_x4_t(uint32_t r[4], uint32_t addr) {
    asm volatile("ldmatrix.sync.aligned.m8n8.x4.trans.shared.b16 {%0,%1,%2,%3}, [%4];"
                 : "=r"(r[0]), "=r"(r[1]), "=r"(r[2]), "=r"(r[3]) : "r"(addr));
}
__device__ __forceinline__ void mma16816(float c[4], const uint32_t a[4], uint32_t b0, uint32_t b1) {
    asm volatile("mma.sync.aligned.m16n8k16.row.col.f32.bf16.bf16.f32 "
                 "{%0,%1,%2,%3}, {%4,%5,%6,%7}, {%8,%9}, {%0,%1,%2,%3};"
                 : "+f"(c[0]), "+f"(c[1]), "+f"(c[2]), "+f"(c[3])
                 : "r"(a[0]), "r"(a[1]), "r"(a[2]), "r"(a[3]), "r"(b0), "r"(b1));
}

__device__ __forceinline__ unsigned pack2(bf16 a, bf16 b) {
    __nv_bfloat162 t(a, b);
    return *reinterpret_cast<unsigned*>(&t);
}
__device__ __forceinline__ void split1(float v, bf16& h, bf16& l) {
    h = __float2bfloat16(v);
    l = __float2bfloat16(v - __bfloat162float(h));
}

// ---------------------------------------------------------------------------
// acc(128x128) += A(128xK)*B^T, K chunks of 32, 3-stage cp.async ring.
// MMA issue order: term-major, 4-accumulator round robin (reuse distance 4).
// ---------------------------------------------------------------------------
template <bool TRANSB>
__device__ __forceinline__ void mainloop(
    const bf16* __restrict__ Ah, const bf16* __restrict__ Al, int lda,
    const bf16* __restrict__ Bh, const bf16* __restrict__ Bl, int ldb,
    int nch, char* smem, float (&acc)[2][8][4])
{
    const uint32_t su = smem_u32(smem);
    const int tid = threadIdx.x;
    const int lane = tid & 31, w = tid >> 5;
    const int m0w = (w & 3) * 32, n0w = (w >> 2) * 64;

    const int arow = tid >> 1;
    const int ac0  = (tid & 1) * 32;
    const int tkr = tid >> 4, tseg = tid & 15;

    auto load_chunk = [&](int ch, int st) {
        const int k0 = ch * 32;
        const uint32_t base = su + st * STAGE;
        const bf16* pAh = Ah + (size_t)arow * lda + k0 + (ac0 >> 1);
        const bf16* pAl = Al + (size_t)arow * lda + k0 + (ac0 >> 1);
        uint32_t d0 = base + swzN(arow, ac0);
        uint32_t d1 = base + swzN(arow, ac0 + 16);
        cp16(d0, pAh);            cp16(d1, pAh + 8);
        cp16(d0 + ARR, pAl);      cp16(d1 + ARR, pAl + 8);
        if (!TRANSB) {
            const bf16* pBh = Bh + (size_t)arow * ldb + k0 + (ac0 >> 1);
            const bf16* pBl = Bl + (size_t)arow * ldb + k0 + (ac0 >> 1);
            uint32_t e0 = base + 2 * ARR + swzN(arow, ac0);
            uint32_t e1 = base + 2 * ARR + swzN(arow, ac0 + 16);
            cp16(e0, pBh);        cp16(e1, pBh + 8);
            cp16(e0 + ARR, pBl);  cp16(e1 + ARR, pBl + 8);
        } else {
            const bf16* pBh0 = Bh + (size_t)(k0 + tkr) * ldb + tseg * 8;
            const bf16* pBl0 = Bl + (size_t)(k0 + tkr) * ldb + tseg * 8;
            const bf16* pBh1 = Bh + (size_t)(k0 + tkr + 16) * ldb + tseg * 8;
            const bf16* pBl1 = Bl + (size_t)(k0 + tkr + 16) * ldb + tseg * 8;
            uint32_t e0 = base + 2 * ARR + swzT(tkr, tseg * 16);
            uint32_t e1 = base + 2 * ARR + swzT(tkr + 16, tseg * 16);
            cp16(e0, pBh0);       cp16(e0 + ARR, pBl0);
            cp16(e1, pBh1);       cp16(e1 + ARR, pBl1);
        }
    };

    load_chunk(0, 0); cp_commit();
    if (nch > 1) load_chunk(1, 1);
    cp_commit();

    for (int ch = 0; ch < nch; ch++) {
        cp_wait1();
        __syncthreads();
        if (ch + 2 < nch) load_chunk(ch + 2, (ch + 2) % 3);
        cp_commit();

        const uint32_t base = su + (ch % 3) * STAGE;
#pragma unroll
        for (int kk = 0; kk < 2; kk++) {
            uint32_t Af[2][4], Alf[2][4];
            {
                const uint32_t r0 = m0w + (lane & 15);
                const uint32_t c0 = (lane >> 4) * 16 + kk * 32;
#pragma unroll
                for (int mt = 0; mt < 2; mt++) {
                    uint32_t a0 = base + swzN(r0 + mt * 16, c0);
                    ldsm_x4(Af[mt],  a0);
                    ldsm_x4(Alf[mt], a0 + ARR);
                }
            }
#pragma unroll
            for (int p = 0; p < 4; p++) {
                uint32_t q[4], ql[4];
                if (!TRANSB) {
                    const uint32_t r0 = n0w + (lane & 7) + ((lane >> 4) << 3) + p * 16;
                    const uint32_t c0 = ((lane >> 3) & 1) * 16 + kk * 32;
                    uint32_t b0 = base + 2 * ARR + swzN(r0, c0);
                    ldsm_x4(q,  b0);
                    ldsm_x4(ql, b0 + ARR);
                } else {
                    const uint32_t r0 = (lane & 15) + kk * 16;
                    const uint32_t c0 = (lane >> 4) * 16 + n0w * 2 + p * 32;
                    uint32_t b0 = base + 2 * ARR + swzT(r0, c0);
                    ldsm_x4_t(q,  b0);
                    ldsm_x4_t(ql, b0 + ARR);
                }
                const int nt0 = 2 * p, nt1 = 2 * p + 1;
                // term-major, 4-acc round robin: reuse distance 4 per accumulator
                mma16816(acc[0][nt0], Af[0],  q[0],  q[1]);
                mma16816(acc[1][nt0], Af[1],  q[0],  q[1]);
                mma16816(acc[0][nt1], Af[0],  q[2],  q[3]);
                mma16816(acc[1][nt1], Af[1],  q[2],  q[3]);

                mma16816(acc[0][nt0], Af[0],  ql[0], ql[1]);
                mma16816(acc[1][nt0], Af[1],  ql[0], ql[1]);
                mma16816(acc[0][nt1], Af[0],  ql[2], ql[3]);
                mma16816(acc[1][nt1], Af[1],  ql[2], ql[3]);

                mma16816(acc[0][nt0], Alf[0], q[0],  q[1]);
                mma16816(acc[1][nt0], Alf[1], q[0],  q[1]);
                mma16816(acc[0][nt1], Alf[0], q[2],  q[3]);
                mma16816(acc[1][nt1], Alf[1], q[2],  q[3]);
            }
        }
    }
    __syncthreads();
}

// ---------------- precompute: fp32 -> bf16 hi/lo splits ----------------
__global__ __launch_bounds__(256) void convert_x(const float* __restrict__ x)
{
    size_t idx = (size_t)(blockIdx.x * 256 + threadIdx.x) * 4;
    float4 v = *(const float4*)(x + idx);
    bf16 h[4], l[4];
    split1(v.x, h[0], l[0]); split1(v.y, h[1], l[1]);
    split1(v.z, h[2], l[2]); split1(v.w, h[3], l[3]);
    *(uint2*)(g_xh + idx) = make_uint2(pack2(h[0], h[1]), pack2(h[2], h[3]));
    *(uint2*)(g_xl + idx) = make_uint2(pack2(l[0], l[1]), pack2(l[2], l[3]));
}

__global__ __launch_bounds__(256) void convert_w(
    const float* __restrict__ Wq, const float* __restrict__ Wk, const float* __restrict__ Wv)
{
    const float* W = (blockIdx.z == 0) ? Wq : (blockIdx.z == 1) ? Wk : Wv;
    size_t base = (size_t)blockIdx.z * D_ * D_;
    size_t idx = (size_t)(blockIdx.x * 256 + threadIdx.x) * 4;
    float4 v = *(const float4*)(W + idx);
    bf16 h[4], l[4];
    split1(v.x, h[0], l[0]); split1(v.y, h[1], l[1]);
    split1(v.z, h[2], l[2]); split1(v.w, h[3], l[3]);
    *(uint2*)(g_Wh + base + idx) = make_uint2(pack2(h[0], h[1]), pack2(h[2], h[3]));
    *(uint2*)(g_Wl + base + idx) = make_uint2(pack2(l[0], l[1]), pack2(l[2], l[3]));
}

// ---------------- GEMM 1: Q/K/V = x @ W ----------------
__global__ __launch_bounds__(256, 2) void qkv_mm()
{
    extern __shared__ char smem[];
    const int n0 = blockIdx.x * 128, m0 = blockIdx.y * 128, z = blockIdx.z;
    float acc[2][8][4] = {};

    mainloop<true>(g_xh + (size_t)m0 * D_, g_xl + (size_t)m0 * D_, D_,
                   g_Wh + (size_t)z * D_ * D_ + n0,
                   g_Wl + (size_t)z * D_ * D_ + n0, D_,
                   D_ / 32, smem, acc);

    bf16* Oh = (z == 0) ? g_Qh : (z == 1) ? g_Kh : g_Vh;
    bf16* Ol = (z == 0) ? g_Ql : (z == 1) ? g_Kl : g_Vl;
    const int lane = threadIdx.x & 31, w = threadIdx.x >> 5;
    const int m0w = (w & 3) * 32, n0w = (w >> 2) * 64;
#pragma unroll
    for (int mt = 0; mt < 2; mt++)
#pragma unroll
        for (int nt = 0; nt < 8; nt++) {
            int m = m0 + m0w + mt * 16 + (lane >> 2);
            int n = n0 + n0w + nt * 8 + (lane & 3) * 2;
            float* c = acc[mt][nt];
            bf16 h0, l0, h1, l1;
            split1(c[0], h0, l0); split1(c[1], h1, l1);
            *(unsigned*)(Oh + (size_t)m * D_ + n) = pack2(h0, h1);
            *(unsigned*)(Ol + (size_t)m * D_ + n) = pack2(l0, l1);
            split1(c[2], h0, l0); split1(c[3], h1, l1);
            *(unsigned*)(Oh + (size_t)(m + 8) * D_ + n) = pack2(h0, h1);
            *(unsigned*)(Ol + (size_t)(m + 8) * D_ + n) = pack2(l0, l1);
        }
}

// ---------------- GEMM 2: S = Q @ K^T (compact triangular grid) ----------
__global__ __launch_bounds__(256, 2) void qk_mm()
{
    const int i = blockIdx.x, bt = blockIdx.z;
    int qt = (int)((sqrtf(8.0f * i + 1.0f) - 1.0f) * 0.5f);
    while ((qt + 1) * (qt + 2) / 2 <= i) qt++;
    while (qt * (qt + 1) / 2 > i) qt--;
    const int kt = i - qt * (qt + 1) / 2;

    extern __shared__ char smem[];
    float acc[2][8][4] = {};

    const size_t rb = (size_t)bt * N_ * D_;
    mainloop<false>(g_Qh + rb + (size_t)qt * 128 * D_, g_Ql + rb + (size_t)qt * 128 * D_, D_,
                    g_Kh + rb + (size_t)kt * 128 * D_, g_Kl + rb + (size_t)kt * 128 * D_, D_,
                    D_ / 32, smem, acc);

    float* S = g_S + (size_t)bt * N_ * N_;
    const int lane = threadIdx.x & 31, w = threadIdx.x >> 5;
    const int m0w = (w & 3) * 32, n0w = (w >> 2) * 64;
#pragma unroll
    for (int mt = 0; mt < 2; mt++)
#pragma unroll
        for (int nt = 0; nt < 8; nt++) {
            int q = qt * 128 + m0w + mt * 16 + (lane >> 2);
            int n = kt * 128 + n0w + nt * 8 + (lane & 3) * 2;
            float* c = acc[mt][nt];
            *(float2*)(S + (size_t)q * N_ + n)       = make_float2(c[0], c[1]);
            *(float2*)(S + (size_t)(q + 8) * N_ + n) = make_float2(c[2], c[3]);
        }
}

// ---------------- softmax -> P bf16 hi/lo (zero-padded to tile) ----------
__global__ __launch_bounds__(256) void softmax_k()
{
    const int row = blockIdx.x;
    const int bt = row >> 11;
    const int q  = row & (N_ - 1);
    const size_t base = (size_t)bt * N_ * N_ + (size_t)q * N_;
    const float* S = g_S + base;
    const int L = q + 1;
    const int tid = threadIdx.x;
    const float scale = 0.03125f;

    float pv[8];
    float m = -3.4e38f;
#pragma unroll
    for (int kk = 0; kk < 8; kk++) {
        int i = tid + kk * 256;
        pv[kk] = (i < L) ? S[i] : -3.4e38f;
        m = fmaxf(m, pv[kk]);
    }
#pragma unroll
    for (int off = 16; off; off >>= 1) m = fmaxf(m, __shfl_xor_sync(~0u, m, off));
    __shared__ float red[8];
    if ((tid & 31) == 0) red[tid >> 5] = m;
    __syncthreads();
    float mall = red[0];
#pragma unroll
    for (int j = 1; j < 8; j++) mall = fmaxf(mall, red[j]);
    __syncthreads();

    float sum = 0.f;
#pragma unroll
    for (int kk = 0; kk < 8; kk++) {
        int i = tid + kk * 256;
        if (i < L) { pv[kk] = expf((pv[kk] - mall) * scale); sum += pv[kk]; }
    }
#pragma unroll
    for (int off = 16; off; off >>= 1) sum += __shfl_xor_sync(~0u, sum, off);
    if ((tid & 31) == 0) red[tid >> 5] = sum;
    __syncthreads();
    float tot = 0.f;
#pragma unroll
    for (int j = 0; j < 8; j++) tot += red[j];
    const float inv = 1.0f / tot;

    const int Lpad = ((q >> 7) + 1) << 7;
#pragma unroll
    for (int kk = 0; kk < 8; kk++) {
        int i = tid + kk * 256;
        if (i < Lpad) {
            float p = (i < L) ? pv[kk] * inv : 0.f;
            bf16 h, l; split1(p, h, l);
            g_Ph[base + i] = h;
            g_Pl[base + i] = l;
        }
    }
}

// ---------------- GEMM 3: out = P @ V (heavy tiles first) ----------------
__global__ __launch_bounds__(256, 2) void pv_mm(float* __restrict__ out)
{
    const int et = blockIdx.x, qt = (N_ / 128 - 1) - blockIdx.y, bt = blockIdx.z;
    extern __shared__ char smem[];
    float acc[2][8][4] = {};

    const size_t pb = (size_t)bt * N_ * N_ + (size_t)(qt * 128) * N_;
    const size_t vb = (size_t)bt * N_ * D_ + et * 128;
    mainloop<true>(g_Ph + pb, g_Pl + pb, N_,
                   g_Vh + vb, g_Vl + vb, D_,
                   (qt + 1) * 4, smem, acc);

    const int lane = threadIdx.x & 31, w = threadIdx.x >> 5;
    const int m0w = (w & 3) * 32, n0w = (w >> 2) * 64;
#pragma unroll
    for (int mt = 0; mt < 2; mt++)
#pragma unroll
        for (int nt = 0; nt < 8; nt++) {
            int q = qt * 128 + m0w + mt * 16 + (lane >> 2);
            int n = et * 128 + n0w + nt * 8 + (lane & 3) * 2;
            float* c = acc[mt][nt];
            float* O = out + ((size_t)bt * N_ + q) * D_ + n;
            *(float2*)O            = make_float2(c[0], c[1]);
            *(float2*)(O + 8 * D_) = make_float2(c[2], c[3]);
        }
}

// ---------------------------------------------------------------------------
extern "C" void kernel_launch(void* const* d_in, const int* in_sizes, int n_in,
                              void* d_out, int out_size)
{
    const float* x  = (const float*)d_in[0];
    const float* Wq = (const float*)d_in[1];
    const float* Wk = (const float*)d_in[2];
    const float* Wv = (const float*)d_in[3];
    float* out = (float*)d_out;

    cudaFuncSetAttribute(qkv_mm, cudaFuncAttributeMaxDynamicSharedMemorySize, SM_TOTAL);
    cudaFuncSetAttribute(qk_mm,  cudaFuncAttributeMaxDynamicSharedMemorySize, SM_TOTAL);
    cudaFuncSetAttribute(pv_mm,  cudaFuncAttributeMaxDynamicSharedMemorySize, SM_TOTAL);

    const int NT = N_ / 128;                       // 16
    const int NTRI = NT * (NT + 1) / 2;            // 136

    dim3 blk(256);
    convert_x<<<M_TOT * D_ / 4 / 256, blk>>>(x);
    convert_w<<<dim3(D_ * D_ / 4 / 256, 1, 3), blk>>>(Wq, Wk, Wv);
    qkv_mm<<<dim3(D_ / 128, M_TOT / 128, 3), blk, SM_TOTAL>>>();
    qk_mm<<<dim3(NTRI, 1, B_), blk, SM_TOTAL>>>();
    softmax_k<<<M_TOT, blk>>>();
    pv_mm<<<dim3(D_ / 128, NT, B_), blk, SM_TOTAL>>>(out);
}